// round 2
// baseline (speedup 1.0000x reference)
#include <cuda_runtime.h>
#include <math.h>
#include <stdint.h>

#define DMODEL 1024
#define NHEAD  16
#define HDIM   64
#define DFF    2730
#define DHALT  256
#define BATCH  2
#define SEQ    2048
#define NROWS  (BATCH*SEQ)   // 4096

// ---------------- scratch (static device globals: allocation-guard safe) ---------
__device__ float g_h1[(size_t)NROWS*DMODEL];
__device__ float g_qkv[(size_t)NROWS*3*DMODEL];
__device__ float g_attn[(size_t)NROWS*DMODEL];
__device__ float g_x1[(size_t)NROWS*DMODEL];
__device__ float g_h2[(size_t)NROWS*DMODEL];
__device__ float g_u[(size_t)NROWS*DFF];
__device__ float g_v[(size_t)NROWS*DFF];
__device__ float g_hh[(size_t)NROWS*DHALT];

// ---------------- rmsnorm: one block per row --------------------------------
__global__ void rmsnorm_kernel(const float* __restrict__ x, const float* __restrict__ g,
                               float* __restrict__ y) {
    int row = blockIdx.x;
    const float* xr = x + (size_t)row * DMODEL;
    int t = threadIdx.x;
    float v[4];
    float ss = 0.f;
#pragma unroll
    for (int i = 0; i < 4; i++) { v[i] = xr[t + i * 256]; ss += v[i] * v[i]; }
    // warp reduce then cross-warp
    for (int off = 16; off; off >>= 1) ss += __shfl_xor_sync(0xffffffffu, ss, off);
    __shared__ float red[8];
    if ((t & 31) == 0) red[t >> 5] = ss;
    __syncthreads();
    if (t < 8) {
        float s2 = red[t];
        for (int off = 4; off; off >>= 1) s2 += __shfl_xor_sync(0xffu, s2, off);
        if (t == 0) red[0] = s2;
    }
    __syncthreads();
    float inv = rsqrtf(red[0] * (1.0f / DMODEL) + 1e-6f);
    float* yr = y + (size_t)row * DMODEL;
#pragma unroll
    for (int i = 0; i < 4; i++) {
        int c = t + i * 256;
        yr[c] = v[i] * inv * g[c];
    }
}

// ---------------- generic tiled fp32 GEMM: C[M,N] = A[M,K] @ B[K,N] ----------
// MODE 0: plain   MODE 1: C = acc + E[m,n] (residual)   MODE 2: C = gelu(acc + E[n]) (bias)
template <int MODE>
__global__ void gemm_kernel(const float* __restrict__ A, const float* __restrict__ Bm,
                            float* __restrict__ C, const float* __restrict__ E,
                            int M, int K, int N) {
    __shared__ float As[16 * 129];   // [kk][m], padded stride 129 -> conflict-free
    __shared__ float Bs[16 * 64];    // [kk][n]
    int tid = threadIdx.x;
    int tx = tid & 15, ty = tid >> 4;
    int m0 = blockIdx.y * 128, n0 = blockIdx.x * 64;
    float acc[8][4];
#pragma unroll
    for (int i = 0; i < 8; i++)
#pragma unroll
        for (int j = 0; j < 4; j++) acc[i][j] = 0.f;

    for (int k0 = 0; k0 < K; k0 += 16) {
#pragma unroll
        for (int i = 0; i < 8; i++) {           // A tile 128x16
            int e = i * 256 + tid;
            int m = e >> 4, kk = e & 15;
            float val = 0.f;
            if (m0 + m < M && k0 + kk < K) val = A[(size_t)(m0 + m) * K + k0 + kk];
            As[kk * 129 + m] = val;
        }
#pragma unroll
        for (int i = 0; i < 4; i++) {           // B tile 16x64
            int e = i * 256 + tid;
            int kk = e >> 6, n = e & 63;
            float val = 0.f;
            if (k0 + kk < K && n0 + n < N) val = Bm[(size_t)(k0 + kk) * N + n0 + n];
            Bs[kk * 64 + n] = val;
        }
        __syncthreads();
#pragma unroll
        for (int kk = 0; kk < 16; kk++) {
            float a[8], b[4];
#pragma unroll
            for (int i = 0; i < 8; i++) a[i] = As[kk * 129 + ty * 8 + i];
#pragma unroll
            for (int j = 0; j < 4; j++) b[j] = Bs[kk * 64 + tx * 4 + j];
#pragma unroll
            for (int i = 0; i < 8; i++)
#pragma unroll
                for (int j = 0; j < 4; j++) acc[i][j] = fmaf(a[i], b[j], acc[i][j]);
        }
        __syncthreads();
    }
#pragma unroll
    for (int i = 0; i < 8; i++) {
        int m = m0 + ty * 8 + i;
        if (m >= M) continue;
#pragma unroll
        for (int j = 0; j < 4; j++) {
            int n = n0 + tx * 4 + j;
            if (n >= N) continue;
            float r = acc[i][j];
            if (MODE == 1) r += E[(size_t)m * N + n];
            if (MODE == 2) {
                r += E[n];
                r = 0.5f * r * (1.f + erff(r * 0.70710678118654752f));  // exact gelu
            }
            C[(size_t)m * N + n] = r;
        }
    }
}

// ---------------- flash attention: BQ=BK=64, HD=64, online softmax -----------
// grid: (SEQ/64, BATCH*NHEAD), block 256
__global__ void attn_kernel(const float* __restrict__ qkv, float* __restrict__ out) {
    extern __shared__ float sm[];
    float* Qs = sm;               // 64*65
    float* Ks = Qs + 64 * 65;
    float* Vs = Ks + 64 * 65;
    float* Ss = Vs + 64 * 65;
    int tid = threadIdx.x;
    int tx = tid & 15, ty = tid >> 4;
    int bh = blockIdx.y;
    int b = bh >> 4, h = bh & 15;
    int qt0 = blockIdx.x * 64;
    size_t base = (size_t)b * SEQ * 3072;

    // load Q tile (64x64), float4 coalesced
#pragma unroll
    for (int i = 0; i < 4; i++) {
        int e = i * 256 + tid;
        int r = e >> 4, dq = e & 15;
        float4 v = *(const float4*)&qkv[base + (size_t)(qt0 + r) * 3072 + h * 64 + dq * 4];
        float* d = &Qs[r * 65 + dq * 4];
        d[0] = v.x; d[1] = v.y; d[2] = v.z; d[3] = v.w;
    }

    float m_i[4], l_i[4], acc[4][4];
#pragma unroll
    for (int i = 0; i < 4; i++) {
        m_i[i] = -1e30f; l_i[i] = 0.f;
#pragma unroll
        for (int j = 0; j < 4; j++) acc[i][j] = 0.f;
    }

    int jt_max = blockIdx.x;
    for (int jt = 0; jt <= jt_max; jt++) {
        int j0 = jt * 64;
        __syncthreads();   // protect Ks/Vs/Ss from previous iteration's reads (and Q on iter 0)
#pragma unroll
        for (int i = 0; i < 4; i++) {
            int e = i * 256 + tid;
            int r = e >> 4, dq = e & 15;
            float4 kv = *(const float4*)&qkv[base + (size_t)(j0 + r) * 3072 + 1024 + h * 64 + dq * 4];
            float* dk = &Ks[r * 65 + dq * 4];
            dk[0] = kv.x; dk[1] = kv.y; dk[2] = kv.z; dk[3] = kv.w;
            float4 vv = *(const float4*)&qkv[base + (size_t)(j0 + r) * 3072 + 2048 + h * 64 + dq * 4];
            float* dv = &Vs[r * 65 + dq * 4];
            dv[0] = vv.x; dv[1] = vv.y; dv[2] = vv.z; dv[3] = vv.w;
        }
        __syncthreads();

        // S = Q K^T (each thread 4x4)
        float s[4][4];
#pragma unroll
        for (int i = 0; i < 4; i++)
#pragma unroll
            for (int j = 0; j < 4; j++) s[i][j] = 0.f;
#pragma unroll
        for (int d = 0; d < 64; d++) {
            float a[4], bq[4];
#pragma unroll
            for (int i = 0; i < 4; i++) a[i] = Qs[(ty * 4 + i) * 65 + d];
#pragma unroll
            for (int j = 0; j < 4; j++) bq[j] = Ks[(tx * 4 + j) * 65 + d];
#pragma unroll
            for (int i = 0; i < 4; i++)
#pragma unroll
                for (int j = 0; j < 4; j++) s[i][j] = fmaf(a[i], bq[j], s[i][j]);
        }
        bool diag = (jt == jt_max);
#pragma unroll
        for (int i = 0; i < 4; i++)
#pragma unroll
            for (int j = 0; j < 4; j++) {
                s[i][j] *= 0.125f;   // 1/sqrt(64)
                if (diag && (j0 + tx * 4 + j > qt0 + ty * 4 + i)) s[i][j] = -1e30f;
            }

        // online softmax (row reduction across the 16 lanes sharing ty)
#pragma unroll
        for (int i = 0; i < 4; i++) {
            float tm = fmaxf(fmaxf(s[i][0], s[i][1]), fmaxf(s[i][2], s[i][3]));
            for (int off = 8; off; off >>= 1) tm = fmaxf(tm, __shfl_xor_sync(0xffffffffu, tm, off, 16));
            float nm = fmaxf(m_i[i], tm);
            float rs = 0.f;
#pragma unroll
            for (int j = 0; j < 4; j++) { s[i][j] = expf(s[i][j] - nm); rs += s[i][j]; }
            for (int off = 8; off; off >>= 1) rs += __shfl_xor_sync(0xffffffffu, rs, off, 16);
            float f = expf(m_i[i] - nm);
            l_i[i] = l_i[i] * f + rs;
            m_i[i] = nm;
#pragma unroll
            for (int j = 0; j < 4; j++) acc[i][j] *= f;
        }
        // P -> smem, then O += P @ V
#pragma unroll
        for (int i = 0; i < 4; i++)
#pragma unroll
            for (int j = 0; j < 4; j++) Ss[(ty * 4 + i) * 65 + tx * 4 + j] = s[i][j];
        __syncthreads();
#pragma unroll
        for (int jj = 0; jj < 64; jj++) {
            float p[4], vv[4];
#pragma unroll
            for (int i = 0; i < 4; i++) p[i] = Ss[(ty * 4 + i) * 65 + jj];
#pragma unroll
            for (int j = 0; j < 4; j++) vv[j] = Vs[jj * 65 + tx * 4 + j];
#pragma unroll
            for (int i = 0; i < 4; i++)
#pragma unroll
                for (int j = 0; j < 4; j++) acc[i][j] = fmaf(p[i], vv[j], acc[i][j]);
        }
    }
#pragma unroll
    for (int i = 0; i < 4; i++) {
        float inv = 1.f / l_i[i];
        int r = qt0 + ty * 4 + i;
#pragma unroll
        for (int j = 0; j < 4; j++)
            out[(size_t)(b * SEQ + r) * DMODEL + h * 64 + tx * 4 + j] = acc[i][j] * inv;
    }
}

// ---------------- swiglu elementwise: u = silu(u) * v ------------------------
__global__ void swiglu_kernel(float* __restrict__ u, const float* __restrict__ v, int n) {
    int i = blockIdx.x * blockDim.x + threadIdx.x;
    if (i < n) {
        float a = u[i];
        float s = a / (1.f + expf(-a));
        u[i] = s * v[i];
    }
}

// ---------------- halt head: sigmoid(hh @ Wh2 + bh2), cum update ------------
__global__ void halt_kernel(const float* __restrict__ hh, const float* __restrict__ Wh2,
                            const float* __restrict__ bh2, const float* __restrict__ cum,
                            float* __restrict__ halt_out, float* __restrict__ cum_out) {
    int row = blockIdx.x;
    int t = threadIdx.x;
    float p = hh[(size_t)row * DHALT + t] * Wh2[t];
    for (int off = 16; off; off >>= 1) p += __shfl_xor_sync(0xffffffffu, p, off);
    __shared__ float red[8];
    if ((t & 31) == 0) red[t >> 5] = p;
    __syncthreads();
    if (t == 0) {
        float sum = red[0] + red[1] + red[2] + red[3] + red[4] + red[5] + red[6] + red[7] + bh2[0];
        float hp = 1.f / (1.f + expf(-sum));
        float c = cum[row];
        float still = (c < 0.99f) ? 1.f : 0.f;
        halt_out[row] = hp;
        cum_out[row] = c + hp * still;
    }
}

// ---------------- launch ------------------------------------------------------
extern "C" void kernel_launch(void* const* d_in, const int* in_sizes, int n_in,
                              void* d_out, int out_size) {
    const float* x    = (const float*)d_in[0];
    const float* cum  = (const float*)d_in[1];
    const float* g1   = (const float*)d_in[2];
    const float* g2   = (const float*)d_in[3];
    const float* Wqkv = (const float*)d_in[4];
    const float* Wo   = (const float*)d_in[5];
    const float* W1   = (const float*)d_in[6];
    const float* W2   = (const float*)d_in[7];
    const float* W3   = (const float*)d_in[8];
    const float* Wh1  = (const float*)d_in[9];
    const float* bh1  = (const float*)d_in[10];
    const float* Wh2  = (const float*)d_in[11];
    const float* bh2  = (const float*)d_in[12];

    float* outx = (float*)d_out;
    float* outh = outx + (size_t)NROWS * DMODEL;
    float* outc = outh + NROWS;

    float *h1, *qkvb, *attnb, *x1, *h2, *u, *v, *hhp;
    cudaGetSymbolAddress((void**)&h1,   g_h1);
    cudaGetSymbolAddress((void**)&qkvb, g_qkv);
    cudaGetSymbolAddress((void**)&attnb,g_attn);
    cudaGetSymbolAddress((void**)&x1,   g_x1);
    cudaGetSymbolAddress((void**)&h2,   g_h2);
    cudaGetSymbolAddress((void**)&u,    g_u);
    cudaGetSymbolAddress((void**)&v,    g_v);
    cudaGetSymbolAddress((void**)&hhp,  g_hh);

    const int attn_smem = 4 * 64 * 65 * sizeof(float);  // 66560 B
    cudaFuncSetAttribute(attn_kernel, cudaFuncAttributeMaxDynamicSharedMemorySize, attn_smem);

    // 1. h1 = rmsnorm(x, g1)
    rmsnorm_kernel<<<NROWS, 256>>>(x, g1, h1);
    // 2. qkv = h1 @ Wqkv
    gemm_kernel<0><<<dim3((3 * DMODEL + 63) / 64, (NROWS + 127) / 128), 256>>>(
        h1, Wqkv, qkvb, nullptr, NROWS, DMODEL, 3 * DMODEL);
    // 3. attention
    attn_kernel<<<dim3(SEQ / 64, BATCH * NHEAD), 256, attn_smem>>>(qkvb, attnb);
    // 4. x1 = x + attn @ Wo
    gemm_kernel<1><<<dim3((DMODEL + 63) / 64, (NROWS + 127) / 128), 256>>>(
        attnb, Wo, x1, x, NROWS, DMODEL, DMODEL);
    // 5. h2 = rmsnorm(x1, g2)
    rmsnorm_kernel<<<NROWS, 256>>>(x1, g2, h2);
    // 6. u = h2 @ W1, v = h2 @ W2
    gemm_kernel<0><<<dim3((DFF + 63) / 64, (NROWS + 127) / 128), 256>>>(
        h2, W1, u, nullptr, NROWS, DMODEL, DFF);
    gemm_kernel<0><<<dim3((DFF + 63) / 64, (NROWS + 127) / 128), 256>>>(
        h2, W2, v, nullptr, NROWS, DMODEL, DFF);
    // 7. u = silu(u) * v
    {
        int n = NROWS * DFF;
        swiglu_kernel<<<(n + 255) / 256, 256>>>(u, v, n);
    }
    // 8. x (final) = x1 + u @ W3  -> written straight into d_out
    gemm_kernel<1><<<dim3((DMODEL + 63) / 64, (NROWS + 127) / 128), 256>>>(
        u, W3, outx, x1, NROWS, DFF, DMODEL);
    // 9. hh = gelu(x @ Wh1 + bh1)
    gemm_kernel<2><<<dim3((DHALT + 63) / 64, (NROWS + 127) / 128), 256>>>(
        outx, Wh1, hhp, bh1, NROWS, DMODEL, DHALT);
    // 10. halt probs + cum update
    halt_kernel<<<NROWS, 256>>>(hhp, Wh2, bh2, cum, outh, outc);
}